// round 4
// baseline (speedup 1.0000x reference)
#include <cuda_runtime.h>
#include <math.h>

#define H 4096
#define NEXP 64
#define TOPK 8

// device scratch (alloc-free rule: __device__ globals)
__device__ float g_counts[NEXP];
__device__ int   g_fix_count;          // zero-initialized at module load
__device__ int   g_fix_list[16384];

// ---------------------------------------------------------------------------
// Fused gate GEMM (fp32 FFMA) + per-token top-8 + softmax epilogue.
// Block: 256 threads, tile = 64 tokens x 64 experts, K-loop in chunks of 64.
// Flags tokens whose top-10 adjacent gaps are < 1e-4 for exact fixup.
// ---------------------------------------------------------------------------
__global__ __launch_bounds__(256) void gate_gemm_topk(
    const float* __restrict__ x, const float* __restrict__ W,
    float* __restrict__ out, int Ntok)
{
    __shared__ float xs[64][65];   // [token][k]
    __shared__ float ws[64][65];   // [expert][k]

    const int t   = threadIdx.x;
    const int tx  = t & 15;   // expert group (4 experts)
    const int ty  = t >> 4;   // token group  (4 tokens)
    const int tok0 = blockIdx.x * 64;

    float acc[4][4];
#pragma unroll
    for (int i = 0; i < 4; i++)
#pragma unroll
        for (int j = 0; j < 4; j++) acc[i][j] = 0.f;

    const float* xbase = x + (size_t)tok0 * H;

    for (int k0 = 0; k0 < H; k0 += 64) {
#pragma unroll
        for (int i = 0; i < 16; i++) {
            int idx = t + 256 * i;     // 0..4095
            int row = idx >> 6;
            int col = idx & 63;
            xs[row][col] = xbase[(size_t)row * H + k0 + col];
            ws[row][col] = W[(size_t)row * H + k0 + col];
        }
        __syncthreads();

#pragma unroll 16
        for (int kk = 0; kk < 64; kk++) {
            float a0 = xs[ty * 4 + 0][kk];
            float a1 = xs[ty * 4 + 1][kk];
            float a2 = xs[ty * 4 + 2][kk];
            float a3 = xs[ty * 4 + 3][kk];
            float b0 = ws[tx * 4 + 0][kk];
            float b1 = ws[tx * 4 + 1][kk];
            float b2 = ws[tx * 4 + 2][kk];
            float b3 = ws[tx * 4 + 3][kk];
            acc[0][0] = fmaf(a0, b0, acc[0][0]);
            acc[0][1] = fmaf(a0, b1, acc[0][1]);
            acc[0][2] = fmaf(a0, b2, acc[0][2]);
            acc[0][3] = fmaf(a0, b3, acc[0][3]);
            acc[1][0] = fmaf(a1, b0, acc[1][0]);
            acc[1][1] = fmaf(a1, b1, acc[1][1]);
            acc[1][2] = fmaf(a1, b2, acc[1][2]);
            acc[1][3] = fmaf(a1, b3, acc[1][3]);
            acc[2][0] = fmaf(a2, b0, acc[2][0]);
            acc[2][1] = fmaf(a2, b1, acc[2][1]);
            acc[2][2] = fmaf(a2, b2, acc[2][2]);
            acc[2][3] = fmaf(a2, b3, acc[2][3]);
            acc[3][0] = fmaf(a3, b0, acc[3][0]);
            acc[3][1] = fmaf(a3, b1, acc[3][1]);
            acc[3][2] = fmaf(a3, b2, acc[3][2]);
            acc[3][3] = fmaf(a3, b3, acc[3][3]);
        }
        __syncthreads();
    }

    // dump logits into xs (reused): xs[token][expert]
#pragma unroll
    for (int i = 0; i < 4; i++)
#pragma unroll
        for (int j = 0; j < 4; j++)
            xs[ty * 4 + i][tx * 4 + j] = acc[i][j];
    __syncthreads();

    // threads 0..63: one token each. top-10 scan (stable: strict '>' gives
    // lowest index on ties, matching jax.lax.top_k). softmax over top-8.
    if (t < 64) {
        float sv[10];
        int   si[10];
#pragma unroll 1
        for (int j = 0; j < 10; j++) {
            float best = -3.4e38f;
            int   bi   = 0;
            for (int e = 0; e < NEXP; e++) {
                float v = xs[t][e];
                if (v > best) { best = v; bi = e; }
            }
            sv[j] = best;
            si[j] = bi;
            xs[t][bi] = -3.4e38f;
        }

        // gap check over ranks 1..10: if any adjacent gap tiny, flag for
        // exact recompute (ordering is unreliable at fp32 precision there).
        float ming = 3.4e38f;
#pragma unroll
        for (int j = 0; j < 9; j++) ming = fminf(ming, sv[j] - sv[j + 1]);

        int g = tok0 + t;
        if (ming < 1e-4f) {
            int pos = atomicAdd(&g_fix_count, 1);
            g_fix_list[pos] = g;
        }

        float m = sv[0];
        float ex[TOPK];
        float s = 0.f;
#pragma unroll
        for (int j = 0; j < TOPK; j++) { ex[j] = expf(sv[j] - m); s += ex[j]; }
        float inv = 1.f / s;

        float* score_out = out + (size_t)g * TOPK;
        float* idx_out   = out + (size_t)Ntok * TOPK + (size_t)g * TOPK;
#pragma unroll
        for (int j = 0; j < TOPK; j++) {
            score_out[j] = ex[j] * inv;
            idx_out[j]   = (float)si[j];
        }
    }
}

// ---------------------------------------------------------------------------
// Exact fixup: recompute all 64 logits of flagged tokens with TwoProd +
// Neumaier compensated fp32 (error ~1e-13 rel), top-8 in double, overwrite.
// Fixed grid; blocks stride over the flagged list.
// ---------------------------------------------------------------------------
__global__ __launch_bounds__(256) void fixup_kernel(
    const float* __restrict__ x, const float* __restrict__ W,
    float* __restrict__ out, int Ntok)
{
    const int t   = threadIdx.x;
    const int e   = t >> 2;        // expert 0..63
    const int sub = t & 3;         // k-quarter
    const int nfix = g_fix_count;

    __shared__ double lg[NEXP];

    for (int fi = blockIdx.x; fi < nfix; fi += gridDim.x) {
        const int tok = g_fix_list[fi];
        const float* xr = x + (size_t)tok * H;
        const float* wr = W + (size_t)e * H;

        float s = 0.f, c = 0.f;
        const int kb = sub * (H / 4);
#pragma unroll 4
        for (int k = kb; k < kb + H / 4; k++) {
            float xv = xr[k], wv = wr[k];
            float p  = xv * wv;
            float pe = fmaf(xv, wv, -p);          // exact product error
            float tt = s + p;                      // Neumaier 2Sum
            c += (fabsf(s) >= fabsf(p)) ? ((s - tt) + p) : ((p - tt) + s);
            s  = tt;
            c += pe;
        }
        double d = (double)s + (double)c;
        d += __shfl_down_sync(0xffffffffu, d, 1);
        d += __shfl_down_sync(0xffffffffu, d, 2);
        if (sub == 0) lg[e] = d;
        __syncthreads();

        if (t == 0) {
            double sv[TOPK];
            int    si[TOPK];
#pragma unroll 1
            for (int j = 0; j < TOPK; j++) {
                double best = -1e300;
                int    bi   = 0;
                for (int ee = 0; ee < NEXP; ee++) {
                    double v = lg[ee];
                    if (v > best) { best = v; bi = ee; }
                }
                sv[j] = best; si[j] = bi;
                lg[bi] = -1e300;
            }
            float m = (float)sv[0];
            float ex[TOPK];
            float ssum = 0.f;
#pragma unroll
            for (int j = 0; j < TOPK; j++) {
                ex[j] = expf((float)sv[j] - m);
                ssum += ex[j];
            }
            float inv = 1.f / ssum;
            float* score_out = out + (size_t)tok * TOPK;
            float* idx_out   = out + (size_t)Ntok * TOPK + (size_t)tok * TOPK;
#pragma unroll
            for (int j = 0; j < TOPK; j++) {
                score_out[j] = ex[j] * inv;
                idx_out[j]   = (float)si[j];
            }
        }
        __syncthreads();
    }
}

// ---------------------------------------------------------------------------
// Expert usage counts: block b counts selections of expert b.
// ---------------------------------------------------------------------------
__global__ __launch_bounds__(256) void count_kernel(const float* __restrict__ idx_f, int n_sel)
{
    const int e = blockIdx.x;
    int local = 0;
    for (int i = threadIdx.x; i < n_sel; i += 256)
        local += ((int)idx_f[i] == e) ? 1 : 0;

#pragma unroll
    for (int off = 16; off > 0; off >>= 1)
        local += __shfl_down_sync(0xffffffffu, local, off);

    __shared__ int red[8];
    int wid = threadIdx.x >> 5;
    int lid = threadIdx.x & 31;
    if (lid == 0) red[wid] = local;
    __syncthreads();
    if (threadIdx.x == 0) {
        int tot = 0;
#pragma unroll
        for (int w = 0; w < 8; w++) tot += red[w];
        g_counts[e] = (float)tot;
    }
}

// ---------------------------------------------------------------------------
// loss = 0.01 * sum_e (count_e/N - 1/64)^2; also resets fixup counter for
// the next (graph-replayed) pipeline execution.
// ---------------------------------------------------------------------------
__global__ void loss_kernel(float* __restrict__ out, int Ntok)
{
    const int t = threadIdx.x;   // 64 threads
    float d = g_counts[t] / (float)Ntok - (1.0f / 64.0f);
    float v = d * d;
#pragma unroll
    for (int off = 16; off > 0; off >>= 1)
        v += __shfl_down_sync(0xffffffffu, v, off);

    __shared__ float red[2];
    if ((t & 31) == 0) red[t >> 5] = v;
    __syncthreads();
    if (t == 0) {
        out[0] = 0.01f * (red[0] + red[1]);
        g_fix_count = 0;                 // reset for next replay
    }
}

extern "C" void kernel_launch(void* const* d_in, const int* in_sizes, int n_in,
                              void* d_out, int out_size)
{
    const float* x = (const float*)d_in[0];
    const float* W = (const float*)d_in[1];
    float* out = (float*)d_out;

    int Ntok  = in_sizes[0] / H;          // 16384
    int n_sel = Ntok * TOPK;              // 131072

    gate_gemm_topk<<<Ntok / 64, 256>>>(x, W, out, Ntok);
    fixup_kernel<<<128, 256>>>(x, W, out, Ntok);
    count_kernel<<<NEXP, 256>>>(out + (size_t)n_sel, n_sel);
    loss_kernel<<<1, 64>>>(out + (size_t)2 * n_sel, Ntok);
}

// round 7
// speedup vs baseline: 1.4362x; 1.4362x over previous
#include <cuda_runtime.h>
#include <math.h>
#include <stdint.h>

#define H 4096
#define NEXP 64
#define TOPK 8
#define TILE_M 128
#define KC 32
#define NCHUNK (H / KC)          // 128

// padded smem strides (words): stride % 32 == 4 -> fragment LDS conflict-free
#define SA 36                    // A row stride (KC=32 + 4)
#define SB 36                    // B row stride

// smem layout (floats):
//   A bufs: [stage*2+buf] * (128*SA)   4 bufs
//   B bufs: [stage*2+buf] * (64*SB)    4 bufs
#define A_BUF_W   (TILE_M * SA)             // 4608 words
#define B_BUF_W   (NEXP * SB)               // 2304 words
#define B_BASE_W  (4 * A_BUF_W)             // 18432
#define SMEM_W    (B_BASE_W + 4 * B_BUF_W)  // 27648 words = 110592 B
#define LOGIT_STRIDE 65

// device scratch (alloc-free rule)
__device__ float g_counts[NEXP];
__device__ int   g_fix_count;
__device__ int   g_fix_list[16384];
__device__ float g_Whi[NEXP * H];
__device__ float g_Wlo[NEXP * H];

static __device__ __forceinline__ uint32_t cvt_tf32(float f) {
    uint32_t r;
    asm("cvt.rna.tf32.f32 %0, %1;" : "=r"(r) : "f"(f));
    return r;
}

static __device__ __forceinline__ void mma_tf32(float* d, const uint32_t* a, const uint32_t* b) {
    asm volatile(
        "mma.sync.aligned.m16n8k8.row.col.f32.tf32.tf32.f32 "
        "{%0,%1,%2,%3}, {%4,%5,%6,%7}, {%8,%9}, {%0,%1,%2,%3};"
        : "+f"(d[0]), "+f"(d[1]), "+f"(d[2]), "+f"(d[3])
        : "r"(a[0]), "r"(a[1]), "r"(a[2]), "r"(a[3]), "r"(b[0]), "r"(b[1]));
}

// ---------------------------------------------------------------------------
// W pre-split into tf32 hi/lo
// ---------------------------------------------------------------------------
__global__ __launch_bounds__(256) void wsplit(const float* __restrict__ W) {
    const int n4 = NEXP * H / 4;
    for (int f = blockIdx.x * 256 + threadIdx.x; f < n4; f += gridDim.x * 256) {
        float4 w = ((const float4*)W)[f];
        float4 hi, lo;
        hi.x = __uint_as_float(cvt_tf32(w.x));
        hi.y = __uint_as_float(cvt_tf32(w.y));
        hi.z = __uint_as_float(cvt_tf32(w.z));
        hi.w = __uint_as_float(cvt_tf32(w.w));
        lo.x = __uint_as_float(cvt_tf32(w.x - hi.x));
        lo.y = __uint_as_float(cvt_tf32(w.y - hi.y));
        lo.z = __uint_as_float(cvt_tf32(w.z - hi.z));
        lo.w = __uint_as_float(cvt_tf32(w.w - hi.w));
        ((float4*)g_Whi)[f] = hi;
        ((float4*)g_Wlo)[f] = lo;
    }
}

// ---------------------------------------------------------------------------
// 3xTF32 split GEMM via mma.sync (m16n8k8) + fused top-8/softmax epilogue.
// CTA = 128 tokens x 64 experts. 8 warps: mw = wid&3 (32 tokens each),
// nw = wid>>2 (32 experts each). K double-buffered in 32-wide chunks.
// ---------------------------------------------------------------------------
__global__ __launch_bounds__(256, 1) void gate_mma(
    const float* __restrict__ x, float* __restrict__ out, int Ntok)
{
    extern __shared__ float sm[];
    const int t    = threadIdx.x;
    const int wid  = t >> 5;
    const int lane = t & 31;
    const int gid  = lane >> 2;      // 0..7
    const int tig  = lane & 3;       // 0..3
    const int mw   = wid & 3;        // token-warp  (32 tokens)
    const int nw   = wid >> 2;       // expert-warp (32 experts)
    const int tok0 = blockIdx.x * TILE_M;

    float d[2][4][4];                // [mtile][ntile][frag]
#pragma unroll
    for (int i = 0; i < 2; i++)
#pragma unroll
        for (int j = 0; j < 4; j++)
#pragma unroll
            for (int k = 0; k < 4; k++) d[i][j][k] = 0.f;

    const float* xb = x + (size_t)tok0 * H;

    float4 ra[4];        // A prefetch: 4 float4/thread/chunk
    float4 rbh[2], rbl[2];

    // ---- prologue: load + convert + store chunk 0 into stage 0 ----
#pragma unroll
    for (int i = 0; i < 4; i++) {
        int f = t + 256 * i;                 // 0..1023 float4
        int row = f >> 3, c4 = f & 7;
        ra[i] = *(const float4*)(xb + (size_t)row * H + c4 * 4);
    }
#pragma unroll
    for (int i = 0; i < 2; i++) {
        int f = t + 256 * i;                 // 0..511
        int row = f >> 3, c4 = f & 7;
        rbh[i] = *(const float4*)(g_Whi + (size_t)row * H + c4 * 4);
        rbl[i] = *(const float4*)(g_Wlo + (size_t)row * H + c4 * 4);
    }
    {
        const int st = 0;
#pragma unroll
        for (int i = 0; i < 4; i++) {
            int f = t + 256 * i;
            int row = f >> 3, c4 = f & 7;
            float4 v = ra[i];
            float4 hi, lo;
            hi.x = __uint_as_float(cvt_tf32(v.x)); lo.x = __uint_as_float(cvt_tf32(v.x - hi.x));
            hi.y = __uint_as_float(cvt_tf32(v.y)); lo.y = __uint_as_float(cvt_tf32(v.y - hi.y));
            hi.z = __uint_as_float(cvt_tf32(v.z)); lo.z = __uint_as_float(cvt_tf32(v.z - hi.z));
            hi.w = __uint_as_float(cvt_tf32(v.w)); lo.w = __uint_as_float(cvt_tf32(v.w - hi.w));
            *(float4*)(sm + (st * 2 + 0) * A_BUF_W + row * SA + c4 * 4) = hi;
            *(float4*)(sm + (st * 2 + 1) * A_BUF_W + row * SA + c4 * 4) = lo;
        }
#pragma unroll
        for (int i = 0; i < 2; i++) {
            int f = t + 256 * i;
            int row = f >> 3, c4 = f & 7;
            *(float4*)(sm + B_BASE_W + (st * 2 + 0) * B_BUF_W + row * SB + c4 * 4) = rbh[i];
            *(float4*)(sm + B_BASE_W + (st * 2 + 1) * B_BUF_W + row * SB + c4 * 4) = rbl[i];
        }
    }
    __syncthreads();

    // ---- main loop ----
    for (int c = 0; c < NCHUNK; c++) {
        const int s = c & 1;
        const bool more = (c + 1 < NCHUNK);

        if (more) {
            const float* xc = xb + (size_t)(c + 1) * KC;
#pragma unroll
            for (int i = 0; i < 4; i++) {
                int f = t + 256 * i;
                int row = f >> 3, c4 = f & 7;
                ra[i] = *(const float4*)(xc + (size_t)row * H + c4 * 4);
            }
#pragma unroll
            for (int i = 0; i < 2; i++) {
                int f = t + 256 * i;
                int row = f >> 3, c4 = f & 7;
                rbh[i] = *(const float4*)(g_Whi + (size_t)row * H + (c + 1) * KC + c4 * 4);
                rbl[i] = *(const float4*)(g_Wlo + (size_t)row * H + (c + 1) * KC + c4 * 4);
            }
        }

        // MMA over 4 K-slabs of this chunk
        const float* Ah = sm + (s * 2 + 0) * A_BUF_W;
        const float* Al = sm + (s * 2 + 1) * A_BUF_W;
        const float* Bh = sm + B_BASE_W + (s * 2 + 0) * B_BUF_W;
        const float* Bl = sm + B_BASE_W + (s * 2 + 1) * B_BUF_W;
#pragma unroll
        for (int slab = 0; slab < 4; slab++) {
            const int k0 = slab * 8;
            uint32_t ah[2][4], al[2][4], bh[4][2], bl[4][2];
#pragma unroll
            for (int mt = 0; mt < 2; mt++) {
                int r = mw * 32 + mt * 16 + gid;
                ah[mt][0] = __float_as_uint(Ah[(r    ) * SA + k0 + tig    ]);
                ah[mt][1] = __float_as_uint(Ah[(r + 8) * SA + k0 + tig    ]);
                ah[mt][2] = __float_as_uint(Ah[(r    ) * SA + k0 + tig + 4]);
                ah[mt][3] = __float_as_uint(Ah[(r + 8) * SA + k0 + tig + 4]);
                al[mt][0] = __float_as_uint(Al[(r    ) * SA + k0 + tig    ]);
                al[mt][1] = __float_as_uint(Al[(r + 8) * SA + k0 + tig    ]);
                al[mt][2] = __float_as_uint(Al[(r    ) * SA + k0 + tig + 4]);
                al[mt][3] = __float_as_uint(Al[(r + 8) * SA + k0 + tig + 4]);
            }
#pragma unroll
            for (int nt = 0; nt < 4; nt++) {
                int e = nw * 32 + nt * 8 + gid;
                bh[nt][0] = __float_as_uint(Bh[e * SB + k0 + tig    ]);
                bh[nt][1] = __float_as_uint(Bh[e * SB + k0 + tig + 4]);
                bl[nt][0] = __float_as_uint(Bl[e * SB + k0 + tig    ]);
                bl[nt][1] = __float_as_uint(Bl[e * SB + k0 + tig + 4]);
            }
#pragma unroll
            for (int mt = 0; mt < 2; mt++)
#pragma unroll
                for (int nt = 0; nt < 4; nt++) {
                    mma_tf32(d[mt][nt], ah[mt], bh[nt]);   // hi*hi
                    mma_tf32(d[mt][nt], ah[mt], bl[nt]);   // hi*lo
                    mma_tf32(d[mt][nt], al[mt], bh[nt]);   // lo*hi
                }
        }

        if (more) {
            const int st = s ^ 1;
#pragma unroll
            for (int i = 0; i < 4; i++) {
                int f = t + 256 * i;
                int row = f >> 3, c4 = f & 7;
                float4 v = ra[i];
                float4 hi, lo;
                hi.x = __uint_as_float(cvt_tf32(v.x)); lo.x = __uint_as_float(cvt_tf32(v.x - hi.x));
                hi.y = __uint_as_float(cvt_tf32(v.y)); lo.y = __uint_as_float(cvt_tf32(v.y - hi.y));
                hi.z = __uint_as_float(cvt_tf32(v.z)); lo.z = __uint_as_float(cvt_tf32(v.z - hi.z));
                hi.w = __uint_as_float(cvt_tf32(v.w)); lo.w = __uint_as_float(cvt_tf32(v.w - hi.w));
                *(float4*)(sm + (st * 2 + 0) * A_BUF_W + row * SA + c4 * 4) = hi;
                *(float4*)(sm + (st * 2 + 1) * A_BUF_W + row * SA + c4 * 4) = lo;
            }
#pragma unroll
            for (int i = 0; i < 2; i++) {
                int f = t + 256 * i;
                int row = f >> 3, c4 = f & 7;
                *(float4*)(sm + B_BASE_W + (st * 2 + 0) * B_BUF_W + row * SB + c4 * 4) = rbh[i];
                *(float4*)(sm + B_BASE_W + (st * 2 + 1) * B_BUF_W + row * SB + c4 * 4) = rbl[i];
            }
        }
        __syncthreads();
    }

    // ---- write D fragments to smem logits [128][65] ----
    float* logits = sm;
#pragma unroll
    for (int mt = 0; mt < 2; mt++)
#pragma unroll
        for (int nt = 0; nt < 4; nt++) {
            int r = mw * 32 + mt * 16 + gid;
            int cc = nw * 32 + nt * 8 + 2 * tig;
            logits[(r    ) * LOGIT_STRIDE + cc    ] = d[mt][nt][0];
            logits[(r    ) * LOGIT_STRIDE + cc + 1] = d[mt][nt][1];
            logits[(r + 8) * LOGIT_STRIDE + cc    ] = d[mt][nt][2];
            logits[(r + 8) * LOGIT_STRIDE + cc + 1] = d[mt][nt][3];
        }
    __syncthreads();

    // ---- epilogue: top-10 scan + softmax + gap flag (validated in R4) ----
    if (t < TILE_M) {
        const float* row = logits + t * LOGIT_STRIDE;
        float sv[10]; int si[10];
        unsigned long long used = 0ull;
#pragma unroll 1
        for (int j = 0; j < 10; j++) {
            float best = -3.4e38f; int bi = 0;
#pragma unroll
            for (int e = 0; e < NEXP; e++) {
                float v = row[e];
                if (!((used >> e) & 1ull) && v > best) { best = v; bi = e; }
            }
            used |= 1ull << bi;
            sv[j] = best; si[j] = bi;
        }
        float ming = 3.4e38f;
#pragma unroll
        for (int j = 0; j < 9; j++) ming = fminf(ming, sv[j] - sv[j + 1]);

        const int g = tok0 + t;
        if (ming < 1e-4f) {
            int pos = atomicAdd(&g_fix_count, 1);
            g_fix_list[pos] = g;
        }
        float m = sv[0], ex[TOPK], ssum = 0.f;
#pragma unroll
        for (int j = 0; j < TOPK; j++) { ex[j] = expf(sv[j] - m); ssum += ex[j]; }
        float inv = 1.f / ssum;
        float* score_out = out + (size_t)g * TOPK;
        float* idx_out   = out + (size_t)Ntok * TOPK + (size_t)g * TOPK;
#pragma unroll
        for (int j = 0; j < TOPK; j++) {
            score_out[j] = ex[j] * inv;
            idx_out[j]   = (float)si[j];
        }
    }
}

// ---------------------------------------------------------------------------
// Exact fixup (unchanged from passing R3/R4)
// ---------------------------------------------------------------------------
__global__ __launch_bounds__(256) void fixup_kernel(
    const float* __restrict__ x, const float* __restrict__ W,
    float* __restrict__ out, int Ntok)
{
    const int t = threadIdx.x;
    const int e = t >> 2;
    const int sub = t & 3;
    const int nfix = g_fix_count;

    __shared__ double lg[NEXP];

    for (int fi = blockIdx.x; fi < nfix; fi += gridDim.x) {
        const int tok = g_fix_list[fi];
        const float* xr = x + (size_t)tok * H;
        const float* wr = W + (size_t)e * H;

        float s = 0.f, c = 0.f;
        const int kb = sub * (H / 4);
#pragma unroll 4
        for (int k = kb; k < kb + H / 4; k++) {
            float xv = xr[k], wv = wr[k];
            float p  = xv * wv;
            float pe = fmaf(xv, wv, -p);
            float tt = s + p;
            c += (fabsf(s) >= fabsf(p)) ? ((s - tt) + p) : ((p - tt) + s);
            s  = tt;
            c += pe;
        }
        double dd = (double)s + (double)c;
        dd += __shfl_down_sync(0xffffffffu, dd, 1);
        dd += __shfl_down_sync(0xffffffffu, dd, 2);
        if (sub == 0) lg[e] = dd;
        __syncthreads();

        if (t == 0) {
            double sv[TOPK]; int si[TOPK];
#pragma unroll 1
            for (int j = 0; j < TOPK; j++) {
                double best = -1e300; int bi = 0;
                for (int ee = 0; ee < NEXP; ee++) {
                    double v = lg[ee];
                    if (v > best) { best = v; bi = ee; }
                }
                sv[j] = best; si[j] = bi;
                lg[bi] = -1e300;
            }
            float m = (float)sv[0], ex[TOPK], ssum = 0.f;
#pragma unroll
            for (int j = 0; j < TOPK; j++) { ex[j] = expf((float)sv[j] - m); ssum += ex[j]; }
            float inv = 1.f / ssum;
            float* score_out = out + (size_t)tok * TOPK;
            float* idx_out   = out + (size_t)Ntok * TOPK + (size_t)tok * TOPK;
#pragma unroll
            for (int j = 0; j < TOPK; j++) {
                score_out[j] = ex[j] * inv;
                idx_out[j]   = (float)si[j];
            }
        }
        __syncthreads();
    }
}

__global__ __launch_bounds__(256) void count_kernel(const float* __restrict__ idx_f, int n_sel)
{
    const int e = blockIdx.x;
    int local = 0;
    for (int i = threadIdx.x; i < n_sel; i += 256)
        local += ((int)idx_f[i] == e) ? 1 : 0;
#pragma unroll
    for (int off = 16; off > 0; off >>= 1)
        local += __shfl_down_sync(0xffffffffu, local, off);
    __shared__ int red[8];
    int w = threadIdx.x >> 5, l = threadIdx.x & 31;
    if (l == 0) red[w] = local;
    __syncthreads();
    if (threadIdx.x == 0) {
        int tot = 0;
#pragma unroll
        for (int i = 0; i < 8; i++) tot += red[i];
        g_counts[e] = (float)tot;
    }
}

__global__ void loss_kernel(float* __restrict__ out, int Ntok)
{
    const int t = threadIdx.x;   // 64
    float dd = g_counts[t] / (float)Ntok - (1.0f / 64.0f);
    float v = dd * dd;
#pragma unroll
    for (int off = 16; off > 0; off >>= 1)
        v += __shfl_down_sync(0xffffffffu, v, off);
    __shared__ float red[2];
    if ((t & 31) == 0) red[t >> 5] = v;
    __syncthreads();
    if (t == 0) {
        out[0] = 0.01f * (red[0] + red[1]);
        g_fix_count = 0;    // reset for next graph replay
    }
}

extern "C" void kernel_launch(void* const* d_in, const int* in_sizes, int n_in,
                              void* d_out, int out_size)
{
    const float* x = (const float*)d_in[0];
    const float* W = (const float*)d_in[1];
    float* out = (float*)d_out;

    int Ntok  = in_sizes[0] / H;     // 16384
    int n_sel = Ntok * TOPK;         // 131072

    static int configured = 0;
    if (!configured) {
        cudaFuncSetAttribute(gate_mma, cudaFuncAttributeMaxDynamicSharedMemorySize,
                             SMEM_W * 4);
        configured = 1;
    }

    wsplit<<<64, 256>>>(W);
    gate_mma<<<Ntok / TILE_M, 256, SMEM_W * 4>>>(x, out, Ntok);
    fixup_kernel<<<128, 256>>>(x, W, out, Ntok);
    count_kernel<<<NEXP, 256>>>(out + (size_t)n_sel, n_sel);
    loss_kernel<<<1, 64>>>(out + (size_t)2 * n_sel, Ntok);
}

// round 8
// speedup vs baseline: 1.5879x; 1.1056x over previous
#include <cuda_runtime.h>
#include <cuda_bf16.h>
#include <math.h>
#include <stdint.h>

#define H 4096
#define NEXP 64
#define TOPK 8
#define TILE_M 128
#define KC 32
#define NCHUNK (H / KC)          // 128
#define SAH 40                   // smem row stride in halves (80 B: ldmatrix conflict-free)

#define A_BUF_B (TILE_M * SAH * 2)          // 10240 B
#define B_BUF_B (NEXP * SAH * 2)            // 5120 B
#define B_BASE_B (4 * A_BUF_B)              // 40960
#define SMEM_B  (B_BASE_B + 4 * B_BUF_B)    // 61440 B
#define LOGIT_STRIDE 65

// device scratch (alloc-free rule)
__device__ int      g_icounts[NEXP];
__device__ int      g_fix_count;
__device__ int      g_fix_list[16384];
__device__ uint32_t g_Whi[NEXP * H / 2];    // bf16x2-packed W hi
__device__ uint32_t g_Wlo[NEXP * H / 2];    // bf16x2-packed W residual

static __device__ __forceinline__ uint32_t s2u(const void* p) {
    uint32_t a;
    asm("{ .reg .u64 t; cvta.to.shared.u64 t, %1; cvt.u32.u64 %0, t; }" : "=r"(a) : "l"(p));
    return a;
}
static __device__ __forceinline__ void ldsm4(uint32_t* r, uint32_t addr) {
    asm volatile("ldmatrix.sync.aligned.m8n8.x4.shared.b16 {%0,%1,%2,%3}, [%4];"
                 : "=r"(r[0]), "=r"(r[1]), "=r"(r[2]), "=r"(r[3]) : "r"(addr));
}
static __device__ __forceinline__ void mma_bf16(float* d, const uint32_t* a, const uint32_t* b) {
    asm volatile(
        "mma.sync.aligned.m16n8k16.row.col.f32.bf16.bf16.f32 "
        "{%0,%1,%2,%3}, {%4,%5,%6,%7}, {%8,%9}, {%0,%1,%2,%3};"
        : "+f"(d[0]), "+f"(d[1]), "+f"(d[2]), "+f"(d[3])
        : "r"(a[0]), "r"(a[1]), "r"(a[2]), "r"(a[3]), "r"(b[0]), "r"(b[1]));
}
static __device__ __forceinline__ uint32_t pack_hi(float x, float y, float& hx, float& hy) {
    __nv_bfloat162 h = __floats2bfloat162_rn(x, y);
    hx = __bfloat162float(h.x);
    hy = __bfloat162float(h.y);
    return *(uint32_t*)&h;
}
static __device__ __forceinline__ uint32_t pack_lo(float rx, float ry) {
    __nv_bfloat162 l = __floats2bfloat162_rn(rx, ry);
    return *(uint32_t*)&l;
}

// ---------------------------------------------------------------------------
// W pre-split into bf16 hi/lo (packed pairs); also zeroes expert counters.
// ---------------------------------------------------------------------------
__global__ __launch_bounds__(256) void wsplit(const float* __restrict__ W) {
    if (blockIdx.x == 0 && threadIdx.x < NEXP) g_icounts[threadIdx.x] = 0;
    const int n2 = NEXP * H / 2;
    for (int p = blockIdx.x * 256 + threadIdx.x; p < n2; p += gridDim.x * 256) {
        float2 w = ((const float2*)W)[p];
        float hx, hy;
        uint32_t hi = pack_hi(w.x, w.y, hx, hy);
        uint32_t lo = pack_lo(w.x - hx, w.y - hy);
        g_Whi[p] = hi;
        g_Wlo[p] = lo;
    }
}

// ---------------------------------------------------------------------------
// 3x bf16-split GEMM via mma.sync m16n8k16 + ldmatrix, fused top-8/softmax
// epilogue with expert counting. CTA = 128 tokens x 64 experts, 8 warps
// (mw = wid&3: 32 tokens, nw = wid>>2: 32 experts), K double-buffered.
// ---------------------------------------------------------------------------
__global__ __launch_bounds__(256, 1) void gate_mma(
    const float* __restrict__ x, float* __restrict__ out, int Ntok)
{
    extern __shared__ char smem[];
    float* smf = (float*)smem;
    const uint32_t sb = s2u(smem);
    __shared__ int scnt[NEXP];

    const int t    = threadIdx.x;
    const int wid  = t >> 5;
    const int lane = t & 31;
    const int gid  = lane >> 2;
    const int tig  = lane & 3;
    const int mw   = wid & 3;
    const int nw   = wid >> 2;
    const int tok0 = blockIdx.x * TILE_M;

    if (t < NEXP) scnt[t] = 0;

    float d[2][4][4];
#pragma unroll
    for (int i = 0; i < 2; i++)
#pragma unroll
        for (int j = 0; j < 4; j++)
#pragma unroll
            for (int k = 0; k < 4; k++) d[i][j][k] = 0.f;

    const float* xb = x + (size_t)tok0 * H;

    float4 ra[4];
    uint4  rwh, rwl;

    // ---- prologue: chunk 0 ----
#pragma unroll
    for (int i = 0; i < 4; i++) {
        int f = t + 256 * i;                  // 0..1023 float4
        int row = f >> 3, c4 = f & 7;
        ra[i] = *(const float4*)(xb + (size_t)row * H + c4 * 4);
    }
    {
        int row = t >> 2, cc = t & 3;
        rwh = ((const uint4*)g_Whi)[row * (H / 8) + cc];
        rwl = ((const uint4*)g_Wlo)[row * (H / 8) + cc];
    }
    // convert + store stage 0
    {
#pragma unroll
        for (int i = 0; i < 4; i++) {
            int f = t + 256 * i;
            int row = f >> 3, c4 = f & 7;
            float4 v = ra[i];
            float hx, hy, hz, hw;
            uint2 hi, lo;
            hi.x = pack_hi(v.x, v.y, hx, hy);
            hi.y = pack_hi(v.z, v.w, hz, hw);
            lo.x = pack_lo(v.x - hx, v.y - hy);
            lo.y = pack_lo(v.z - hz, v.w - hw);
            *(uint2*)(smem + 0 * A_BUF_B + row * 80 + c4 * 8) = hi;
            *(uint2*)(smem + 1 * A_BUF_B + row * 80 + c4 * 8) = lo;
        }
        int row = t >> 2, cc = t & 3;
        *(uint4*)(smem + B_BASE_B + 0 * B_BUF_B + row * 80 + cc * 16) = rwh;
        *(uint4*)(smem + B_BASE_B + 1 * B_BUF_B + row * 80 + cc * 16) = rwl;
    }
    __syncthreads();

    // ---- main loop ----
    for (int c = 0; c < NCHUNK; c++) {
        const int s = c & 1;
        const bool more = (c + 1 < NCHUNK);

        if (more) {
            const float* xc = xb + (size_t)(c + 1) * KC;
#pragma unroll
            for (int i = 0; i < 4; i++) {
                int f = t + 256 * i;
                int row = f >> 3, c4 = f & 7;
                ra[i] = *(const float4*)(xc + (size_t)row * H + c4 * 4);
            }
            int row = t >> 2, cc = t & 3;
            rwh = ((const uint4*)g_Whi)[row * (H / 8) + (c + 1) * 4 + cc];
            rwl = ((const uint4*)g_Wlo)[row * (H / 8) + (c + 1) * 4 + cc];
        }

        const uint32_t Ah = sb + (s * 2 + 0) * A_BUF_B;
        const uint32_t Al = sb + (s * 2 + 1) * A_BUF_B;
        const uint32_t Bh = sb + B_BASE_B + (s * 2 + 0) * B_BUF_B;
        const uint32_t Bl = sb + B_BASE_B + (s * 2 + 1) * B_BUF_B;

#pragma unroll
        for (int ks = 0; ks < 2; ks++) {
            uint32_t ah[2][4], al[2][4], bh[2][4], bl[2][4];
            const uint32_t arow = mw * 32 + (lane & 15);
            const uint32_t aoff = arow * 80 + ks * 32 + (lane >> 4) * 16;
#pragma unroll
            for (int mt = 0; mt < 2; mt++) {
                ldsm4(ah[mt], Ah + aoff + mt * 16 * 80);
                ldsm4(al[mt], Al + aoff + mt * 16 * 80);
            }
            const uint32_t nrow = nw * 32 + (lane & 7) + ((lane >> 4) << 3);
            const uint32_t boff = nrow * 80 + ks * 32 + ((lane >> 3) & 1) * 16;
#pragma unroll
            for (int p = 0; p < 2; p++) {
                ldsm4(bh[p], Bh + boff + p * 16 * 80);
                ldsm4(bl[p], Bl + boff + p * 16 * 80);
            }
#pragma unroll
            for (int mt = 0; mt < 2; mt++)
#pragma unroll
                for (int nt = 0; nt < 4; nt++) {
                    const uint32_t* bhp = &bh[nt >> 1][(nt & 1) * 2];
                    const uint32_t* blp = &bl[nt >> 1][(nt & 1) * 2];
                    mma_bf16(d[mt][nt], ah[mt], bhp);   // hi*hi
                    mma_bf16(d[mt][nt], ah[mt], blp);   // hi*lo
                    mma_bf16(d[mt][nt], al[mt], bhp);   // lo*hi
                }
        }

        if (more) {
            const int st = s ^ 1;
#pragma unroll
            for (int i = 0; i < 4; i++) {
                int f = t + 256 * i;
                int row = f >> 3, c4 = f & 7;
                float4 v = ra[i];
                float hx, hy, hz, hw;
                uint2 hi, lo;
                hi.x = pack_hi(v.x, v.y, hx, hy);
                hi.y = pack_hi(v.z, v.w, hz, hw);
                lo.x = pack_lo(v.x - hx, v.y - hy);
                lo.y = pack_lo(v.z - hz, v.w - hw);
                *(uint2*)(smem + (st * 2 + 0) * A_BUF_B + row * 80 + c4 * 8) = hi;
                *(uint2*)(smem + (st * 2 + 1) * A_BUF_B + row * 80 + c4 * 8) = lo;
            }
            int row = t >> 2, cc = t & 3;
            *(uint4*)(smem + B_BASE_B + (st * 2 + 0) * B_BUF_B + row * 80 + cc * 16) = rwh;
            *(uint4*)(smem + B_BASE_B + (st * 2 + 1) * B_BUF_B + row * 80 + cc * 16) = rwl;
        }
        __syncthreads();
    }

    // ---- D fragments -> smem logits [128][65] ----
#pragma unroll
    for (int mt = 0; mt < 2; mt++)
#pragma unroll
        for (int nt = 0; nt < 4; nt++) {
            int r = mw * 32 + mt * 16 + gid;
            int cc = nw * 32 + nt * 8 + 2 * tig;
            smf[(r    ) * LOGIT_STRIDE + cc    ] = d[mt][nt][0];
            smf[(r    ) * LOGIT_STRIDE + cc + 1] = d[mt][nt][1];
            smf[(r + 8) * LOGIT_STRIDE + cc    ] = d[mt][nt][2];
            smf[(r + 8) * LOGIT_STRIDE + cc + 1] = d[mt][nt][3];
        }
    __syncthreads();

    // ---- epilogue: top-10 scan + softmax + gap flag + counting ----
    if (t < TILE_M) {
        const float* row = smf + t * LOGIT_STRIDE;
        float sv[10]; int si[10];
        unsigned long long used = 0ull;
#pragma unroll 1
        for (int j = 0; j < 10; j++) {
            float best = -3.4e38f; int bi = 0;
#pragma unroll
            for (int e = 0; e < NEXP; e++) {
                float v = row[e];
                if (!((used >> e) & 1ull) && v > best) { best = v; bi = e; }
            }
            used |= 1ull << bi;
            sv[j] = best; si[j] = bi;
        }
        float ming = 3.4e38f;
#pragma unroll
        for (int j = 0; j < 9; j++) ming = fminf(ming, sv[j] - sv[j + 1]);

        const int g = tok0 + t;
        if (ming < 1e-4f) {
            int pos = atomicAdd(&g_fix_count, 1);
            g_fix_list[pos] = g;
        }
        float m = sv[0], ex[TOPK], ssum = 0.f;
#pragma unroll
        for (int j = 0; j < TOPK; j++) { ex[j] = expf(sv[j] - m); ssum += ex[j]; }
        float inv = 1.f / ssum;
        float* score_out = out + (size_t)g * TOPK;
        float* idx_out   = out + (size_t)Ntok * TOPK + (size_t)g * TOPK;
#pragma unroll
        for (int j = 0; j < TOPK; j++) {
            score_out[j] = ex[j] * inv;
            idx_out[j]   = (float)si[j];
            atomicAdd(&scnt[si[j]], 1);
        }
    }
    __syncthreads();
    if (t < NEXP && scnt[t]) atomicAdd(&g_icounts[t], scnt[t]);
}

// ---------------------------------------------------------------------------
// Exact fixup: compensated fp32 recompute for flagged tokens, top-8 in
// double, overwrite outputs, and patch expert counts (int atomics).
// ---------------------------------------------------------------------------
__global__ __launch_bounds__(256) void fixup_kernel(
    const float* __restrict__ x, const float* __restrict__ W,
    float* __restrict__ out, int Ntok)
{
    const int t = threadIdx.x;
    const int e = t >> 2;
    const int sub = t & 3;
    const int nfix = g_fix_count;

    __shared__ double lg[NEXP];

    for (int fi = blockIdx.x; fi < nfix; fi += gridDim.x) {
        const int tok = g_fix_list[fi];
        const float* xr = x + (size_t)tok * H;
        const float* wr = W + (size_t)e * H;

        float s = 0.f, c = 0.f;
        const int kb = sub * (H / 4);
#pragma unroll 4
        for (int k = kb; k < kb + H / 4; k++) {
            float xv = xr[k], wv = wr[k];
            float p  = xv * wv;
            float pe = fmaf(xv, wv, -p);
            float tt = s + p;
            c += (fabsf(s) >= fabsf(p)) ? ((s - tt) + p) : ((p - tt) + s);
            s  = tt;
            c += pe;
        }
        double dd = (double)s + (double)c;
        dd += __shfl_down_sync(0xffffffffu, dd, 1);
        dd += __shfl_down_sync(0xffffffffu, dd, 2);
        if (sub == 0) lg[e] = dd;
        __syncthreads();

        if (t == 0) {
            float* score_out = out + (size_t)tok * TOPK;
            float* idx_out   = out + (size_t)Ntok * TOPK + (size_t)tok * TOPK;
            int olde[TOPK];
#pragma unroll
            for (int j = 0; j < TOPK; j++) olde[j] = (int)idx_out[j];

            double sv[TOPK]; int si[TOPK];
#pragma unroll 1
            for (int j = 0; j < TOPK; j++) {
                double best = -1e300; int bi = 0;
                for (int ee = 0; ee < NEXP; ee++) {
                    double v = lg[ee];
                    if (v > best) { best = v; bi = ee; }
                }
                sv[j] = best; si[j] = bi;
                lg[bi] = -1e300;
            }
            float m = (float)sv[0], ex[TOPK], ssum = 0.f;
#pragma unroll
            for (int j = 0; j < TOPK; j++) { ex[j] = expf((float)sv[j] - m); ssum += ex[j]; }
            float inv = 1.f / ssum;
#pragma unroll
            for (int j = 0; j < TOPK; j++) {
                score_out[j] = ex[j] * inv;
                idx_out[j]   = (float)si[j];
                if (si[j] != olde[j]) {
                    atomicAdd(&g_icounts[si[j]], 1);
                    atomicSub(&g_icounts[olde[j]], 1);
                }
            }
        }
        __syncthreads();
    }
}

// ---------------------------------------------------------------------------
// loss = 0.01 * sum_e (count_e/N - 1/64)^2; resets fixup counter.
// ---------------------------------------------------------------------------
__global__ void loss_kernel(float* __restrict__ out, int Ntok)
{
    const int t = threadIdx.x;   // 64
    float dd = (float)g_icounts[t] / (float)Ntok - (1.0f / 64.0f);
    float v = dd * dd;
#pragma unroll
    for (int off = 16; off > 0; off >>= 1)
        v += __shfl_down_sync(0xffffffffu, v, off);
    __shared__ float red[2];
    if ((t & 31) == 0) red[t >> 5] = v;
    __syncthreads();
    if (t == 0) {
        out[0] = 0.01f * (red[0] + red[1]);
        g_fix_count = 0;    // reset for next graph replay
    }
}

extern "C" void kernel_launch(void* const* d_in, const int* in_sizes, int n_in,
                              void* d_out, int out_size)
{
    const float* x = (const float*)d_in[0];
    const float* W = (const float*)d_in[1];
    float* out = (float*)d_out;

    int Ntok  = in_sizes[0] / H;     // 16384
    int n_sel = Ntok * TOPK;         // 131072
    (void)n_sel;

    cudaFuncSetAttribute(gate_mma, cudaFuncAttributeMaxDynamicSharedMemorySize, SMEM_B);

    wsplit<<<64, 256>>>(W);
    gate_mma<<<Ntok / TILE_M, 256, SMEM_B>>>(x, out, Ntok);
    fixup_kernel<<<128, 256>>>(x, W, out, Ntok);
    loss_kernel<<<1, 64>>>(out + (size_t)2 * n_sel, Ntok);
}

// round 9
// speedup vs baseline: 1.7032x; 1.0726x over previous
#include <cuda_runtime.h>
#include <cuda_bf16.h>
#include <math.h>
#include <stdint.h>

#define H 4096
#define NEXP 64
#define TOPK 8
#define TILE_M 64
#define KC 64
#define NCHUNK (H / KC)          // 64
#define SAB 144                  // smem row stride bytes (64 bf16 + 8 pad)

#define A_BUF_B (TILE_M * SAB)              // 9216 B
#define B_BUF_B (NEXP * SAB)                // 9216 B
#define B_BASE_B (4 * A_BUF_B)              // 36864
#define SMEM_B  (B_BASE_B + 4 * B_BUF_B)    // 73728 B
#define LOGIT_STRIDE 65

// device scratch (alloc-free rule)
__device__ int      g_icounts[NEXP];
__device__ int      g_fix_count;
__device__ int      g_fix_list[16384];
__device__ uint32_t g_Whi[NEXP * H / 2];    // bf16x2-packed W hi
__device__ uint32_t g_Wlo[NEXP * H / 2];    // bf16x2-packed W residual

static __device__ __forceinline__ uint32_t s2u(const void* p) {
    uint32_t a;
    asm("{ .reg .u64 t; cvta.to.shared.u64 t, %1; cvt.u32.u64 %0, t; }" : "=r"(a) : "l"(p));
    return a;
}
static __device__ __forceinline__ void ldsm4(uint32_t* r, uint32_t addr) {
    asm volatile("ldmatrix.sync.aligned.m8n8.x4.shared.b16 {%0,%1,%2,%3}, [%4];"
                 : "=r"(r[0]), "=r"(r[1]), "=r"(r[2]), "=r"(r[3]) : "r"(addr));
}
static __device__ __forceinline__ void mma_bf16(float* d, const uint32_t* a, const uint32_t* b) {
    asm volatile(
        "mma.sync.aligned.m16n8k16.row.col.f32.bf16.bf16.f32 "
        "{%0,%1,%2,%3}, {%4,%5,%6,%7}, {%8,%9}, {%0,%1,%2,%3};"
        : "+f"(d[0]), "+f"(d[1]), "+f"(d[2]), "+f"(d[3])
        : "r"(a[0]), "r"(a[1]), "r"(a[2]), "r"(a[3]), "r"(b[0]), "r"(b[1]));
}
static __device__ __forceinline__ uint32_t pack_hi(float x, float y, float& hx, float& hy) {
    __nv_bfloat162 h = __floats2bfloat162_rn(x, y);
    hx = __bfloat162float(h.x);
    hy = __bfloat162float(h.y);
    return *(uint32_t*)&h;
}
static __device__ __forceinline__ uint32_t pack_lo(float rx, float ry) {
    __nv_bfloat162 l = __floats2bfloat162_rn(rx, ry);
    return *(uint32_t*)&l;
}

// ---------------------------------------------------------------------------
// W pre-split into bf16 hi/lo (packed pairs); also zeroes expert counters.
// ---------------------------------------------------------------------------
__global__ __launch_bounds__(256) void wsplit(const float* __restrict__ W) {
    if (blockIdx.x == 0 && threadIdx.x < NEXP) g_icounts[threadIdx.x] = 0;
    const int n2 = NEXP * H / 2;
    for (int p = blockIdx.x * 256 + threadIdx.x; p < n2; p += gridDim.x * 256) {
        float2 w = ((const float2*)W)[p];
        float hx, hy;
        uint32_t hi = pack_hi(w.x, w.y, hx, hy);
        uint32_t lo = pack_lo(w.x - hx, w.y - hy);
        g_Whi[p] = hi;
        g_Wlo[p] = lo;
    }
}

// ---------------------------------------------------------------------------
// 3x bf16-split GEMM via mma.sync m16n8k16 + ldmatrix, fused top-8/softmax
// epilogue with expert counting. CTA = 64 tokens x 64 experts, 8 warps
// (mw = wid&1: 32 tokens, nw = wid>>1: 16 experts), K double-buffered
// in 64-wide chunks. 2 CTAs/SM for latency hiding.
// ---------------------------------------------------------------------------
__global__ __launch_bounds__(256, 2) void gate_mma(
    const float* __restrict__ x, float* __restrict__ out, int Ntok)
{
    extern __shared__ char smem[];
    float* smf = (float*)smem;
    const uint32_t sb = s2u(smem);
    __shared__ int scnt[NEXP];

    const int t    = threadIdx.x;
    const int wid  = t >> 5;
    const int lane = t & 31;
    const int gid  = lane >> 2;
    const int tig  = lane & 3;
    const int mw   = wid & 1;        // 32 tokens
    const int nw   = wid >> 1;       // 16 experts
    const int tok0 = blockIdx.x * TILE_M;

    if (t < NEXP) scnt[t] = 0;

    float d[2][2][4];
#pragma unroll
    for (int i = 0; i < 2; i++)
#pragma unroll
        for (int j = 0; j < 2; j++)
#pragma unroll
            for (int k = 0; k < 4; k++) d[i][j][k] = 0.f;

    const float* xb = x + (size_t)tok0 * H;

    float4 ra[4];
    uint4  rwh[2], rwl[2];

    // ---- prologue: chunk 0 ----
#pragma unroll
    for (int i = 0; i < 4; i++) {
        int f = t + 256 * i;                  // 0..1023 float4
        int row = f >> 4, c4 = f & 15;
        ra[i] = *(const float4*)(xb + (size_t)row * H + c4 * 4);
    }
#pragma unroll
    for (int i = 0; i < 2; i++) {
        int f = t + 256 * i;                  // 0..511 uint4
        int row = f >> 3, cc = f & 7;
        rwh[i] = ((const uint4*)g_Whi)[row * (H / 8) + cc];
        rwl[i] = ((const uint4*)g_Wlo)[row * (H / 8) + cc];
    }
    {
#pragma unroll
        for (int i = 0; i < 4; i++) {
            int f = t + 256 * i;
            int row = f >> 4, c4 = f & 15;
            float4 v = ra[i];
            float hx, hy, hz, hw;
            uint2 hi, lo;
            hi.x = pack_hi(v.x, v.y, hx, hy);
            hi.y = pack_hi(v.z, v.w, hz, hw);
            lo.x = pack_lo(v.x - hx, v.y - hy);
            lo.y = pack_lo(v.z - hz, v.w - hw);
            *(uint2*)(smem + 0 * A_BUF_B + row * SAB + c4 * 8) = hi;
            *(uint2*)(smem + 1 * A_BUF_B + row * SAB + c4 * 8) = lo;
        }
#pragma unroll
        for (int i = 0; i < 2; i++) {
            int f = t + 256 * i;
            int row = f >> 3, cc = f & 7;
            *(uint4*)(smem + B_BASE_B + 0 * B_BUF_B + row * SAB + cc * 16) = rwh[i];
            *(uint4*)(smem + B_BASE_B + 1 * B_BUF_B + row * SAB + cc * 16) = rwl[i];
        }
    }
    __syncthreads();

    // ---- main loop ----
    for (int c = 0; c < NCHUNK; c++) {
        const int s = c & 1;
        const bool more = (c + 1 < NCHUNK);

        if (more) {
            const float* xc = xb + (size_t)(c + 1) * KC;
#pragma unroll
            for (int i = 0; i < 4; i++) {
                int f = t + 256 * i;
                int row = f >> 4, c4 = f & 15;
                ra[i] = *(const float4*)(xc + (size_t)row * H + c4 * 4);
            }
#pragma unroll
            for (int i = 0; i < 2; i++) {
                int f = t + 256 * i;
                int row = f >> 3, cc = f & 7;
                rwh[i] = ((const uint4*)g_Whi)[row * (H / 8) + (c + 1) * 8 + cc];
                rwl[i] = ((const uint4*)g_Wlo)[row * (H / 8) + (c + 1) * 8 + cc];
            }
        }

        const uint32_t Ah = sb + (s * 2 + 0) * A_BUF_B;
        const uint32_t Al = sb + (s * 2 + 1) * A_BUF_B;
        const uint32_t Bh = sb + B_BASE_B + (s * 2 + 0) * B_BUF_B;
        const uint32_t Bl = sb + B_BASE_B + (s * 2 + 1) * B_BUF_B;

#pragma unroll
        for (int ks = 0; ks < 4; ks++) {
            uint32_t ah[2][4], al[2][4], bh[4], bl[4];
            const uint32_t arow = mw * 32 + (lane & 15);
            const uint32_t aoff = arow * SAB + ks * 32 + (lane >> 4) * 16;
#pragma unroll
            for (int mt = 0; mt < 2; mt++) {
                ldsm4(ah[mt], Ah + aoff + mt * 16 * SAB);
                ldsm4(al[mt], Al + aoff + mt * 16 * SAB);
            }
            const uint32_t nrow = nw * 16 + (lane & 7) + ((lane >> 4) << 3);
            const uint32_t boff = nrow * SAB + ks * 32 + ((lane >> 3) & 1) * 16;
            ldsm4(bh, Bh + boff);
            ldsm4(bl, Bl + boff);
#pragma unroll
            for (int mt = 0; mt < 2; mt++)
#pragma unroll
                for (int nt = 0; nt < 2; nt++) {
                    const uint32_t* bhp = &bh[nt * 2];
                    const uint32_t* blp = &bl[nt * 2];
                    mma_bf16(d[mt][nt], ah[mt], bhp);   // hi*hi
                    mma_bf16(d[mt][nt], ah[mt], blp);   // hi*lo
                    mma_bf16(d[mt][nt], al[mt], bhp);   // lo*hi
                }
        }

        if (more) {
            const int st = s ^ 1;
#pragma unroll
            for (int i = 0; i < 4; i++) {
                int f = t + 256 * i;
                int row = f >> 4, c4 = f & 15;
                float4 v = ra[i];
                float hx, hy, hz, hw;
                uint2 hi, lo;
                hi.x = pack_hi(v.x, v.y, hx, hy);
                hi.y = pack_hi(v.z, v.w, hz, hw);
                lo.x = pack_lo(v.x - hx, v.y - hy);
                lo.y = pack_lo(v.z - hz, v.w - hw);
                *(uint2*)(smem + (st * 2 + 0) * A_BUF_B + row * SAB + c4 * 8) = hi;
                *(uint2*)(smem + (st * 2 + 1) * A_BUF_B + row * SAB + c4 * 8) = lo;
            }
#pragma unroll
            for (int i = 0; i < 2; i++) {
                int f = t + 256 * i;
                int row = f >> 3, cc = f & 7;
                *(uint4*)(smem + B_BASE_B + (st * 2 + 0) * B_BUF_B + row * SAB + cc * 16) = rwh[i];
                *(uint4*)(smem + B_BASE_B + (st * 2 + 1) * B_BUF_B + row * SAB + cc * 16) = rwl[i];
            }
        }
        __syncthreads();
    }

    // ---- D fragments -> smem logits [64][65] ----
#pragma unroll
    for (int mt = 0; mt < 2; mt++)
#pragma unroll
        for (int nt = 0; nt < 2; nt++) {
            int r = mw * 32 + mt * 16 + gid;
            int cc = nw * 16 + nt * 8 + 2 * tig;
            smf[(r    ) * LOGIT_STRIDE + cc    ] = d[mt][nt][0];
            smf[(r    ) * LOGIT_STRIDE + cc + 1] = d[mt][nt][1];
            smf[(r + 8) * LOGIT_STRIDE + cc    ] = d[mt][nt][2];
            smf[(r + 8) * LOGIT_STRIDE + cc + 1] = d[mt][nt][3];
        }
    __syncthreads();

    // ---- epilogue: top-10 scan + softmax + gap flag + counting ----
    if (t < TILE_M) {
        const float* row = smf + t * LOGIT_STRIDE;
        float sv[10]; int si[10];
        unsigned long long used = 0ull;
#pragma unroll 1
        for (int j = 0; j < 10; j++) {
            float best = -3.4e38f; int bi = 0;
#pragma unroll
            for (int e = 0; e < NEXP; e++) {
                float v = row[e];
                if (!((used >> e) & 1ull) && v > best) { best = v; bi = e; }
            }
            used |= 1ull << bi;
            sv[j] = best; si[j] = bi;
        }
        float ming = 3.4e38f;
#pragma unroll
        for (int j = 0; j < 9; j++) ming = fminf(ming, sv[j] - sv[j + 1]);

        const int g = tok0 + t;
        if (ming < 1e-4f) {
            int pos = atomicAdd(&g_fix_count, 1);
            g_fix_list[pos] = g;
        }
        float m = sv[0], ex[TOPK], ssum = 0.f;
#pragma unroll
        for (int j = 0; j < TOPK; j++) { ex[j] = expf(sv[j] - m); ssum += ex[j]; }
        float inv = 1.f / ssum;
        float* score_out = out + (size_t)g * TOPK;
        float* idx_out   = out + (size_t)Ntok * TOPK + (size_t)g * TOPK;
#pragma unroll
        for (int j = 0; j < TOPK; j++) {
            score_out[j] = ex[j] * inv;
            idx_out[j]   = (float)si[j];
            atomicAdd(&scnt[si[j]], 1);
        }
    }
    __syncthreads();
    if (t < NEXP && scnt[t]) atomicAdd(&g_icounts[t], scnt[t]);
}

// ---------------------------------------------------------------------------
// Exact fixup: compensated fp32 recompute for flagged tokens, top-8 in
// double, overwrite outputs, and patch expert counts (int atomics).
// ---------------------------------------------------------------------------
__global__ __launch_bounds__(256) void fixup_kernel(
    const float* __restrict__ x, const float* __restrict__ W,
    float* __restrict__ out, int Ntok)
{
    const int t = threadIdx.x;
    const int e = t >> 2;
    const int sub = t & 3;
    const int nfix = g_fix_count;

    __shared__ double lg[NEXP];

    for (int fi = blockIdx.x; fi < nfix; fi += gridDim.x) {
        const int tok = g_fix_list[fi];
        const float* xr = x + (size_t)tok * H;
        const float* wr = W + (size_t)e * H;

        float s = 0.f, c = 0.f;
        const int kb = sub * (H / 4);
#pragma unroll 4
        for (int k = kb; k < kb + H / 4; k++) {
            float xv = xr[k], wv = wr[k];
            float p  = xv * wv;
            float pe = fmaf(xv, wv, -p);
            float tt = s + p;
            c += (fabsf(s) >= fabsf(p)) ? ((s - tt) + p) : ((p - tt) + s);
            s  = tt;
            c += pe;
        }
        double dd = (double)s + (double)c;
        dd += __shfl_down_sync(0xffffffffu, dd, 1);
        dd += __shfl_down_sync(0xffffffffu, dd, 2);
        if (sub == 0) lg[e] = dd;
        __syncthreads();

        if (t == 0) {
            float* score_out = out + (size_t)tok * TOPK;
            float* idx_out   = out + (size_t)Ntok * TOPK + (size_t)tok * TOPK;
            int olde[TOPK];
#pragma unroll
            for (int j = 0; j < TOPK; j++) olde[j] = (int)idx_out[j];

            double sv[TOPK]; int si[TOPK];
#pragma unroll 1
            for (int j = 0; j < TOPK; j++) {
                double best = -1e300; int bi = 0;
                for (int ee = 0; ee < NEXP; ee++) {
                    double v = lg[ee];
                    if (v > best) { best = v; bi = ee; }
                }
                sv[j] = best; si[j] = bi;
                lg[bi] = -1e300;
            }
            float m = (float)sv[0], ex[TOPK], ssum = 0.f;
#pragma unroll
            for (int j = 0; j < TOPK; j++) { ex[j] = expf((float)sv[j] - m); ssum += ex[j]; }
            float inv = 1.f / ssum;
#pragma unroll
            for (int j = 0; j < TOPK; j++) {
                score_out[j] = ex[j] * inv;
                idx_out[j]   = (float)si[j];
                if (si[j] != olde[j]) {
                    atomicAdd(&g_icounts[si[j]], 1);
                    atomicSub(&g_icounts[olde[j]], 1);
                }
            }
        }
        __syncthreads();
    }
}

// ---------------------------------------------------------------------------
// loss = 0.01 * sum_e (count_e/N - 1/64)^2; resets fixup counter.
// ---------------------------------------------------------------------------
__global__ void loss_kernel(float* __restrict__ out, int Ntok)
{
    const int t = threadIdx.x;   // 64
    float dd = (float)g_icounts[t] / (float)Ntok - (1.0f / 64.0f);
    float v = dd * dd;
#pragma unroll
    for (int off = 16; off > 0; off >>= 1)
        v += __shfl_down_sync(0xffffffffu, v, off);
    __shared__ float red[2];
    if ((t & 31) == 0) red[t >> 5] = v;
    __syncthreads();
    if (t == 0) {
        out[0] = 0.01f * (red[0] + red[1]);
        g_fix_count = 0;    // reset for next graph replay
    }
}

extern "C" void kernel_launch(void* const* d_in, const int* in_sizes, int n_in,
                              void* d_out, int out_size)
{
    const float* x = (const float*)d_in[0];
    const float* W = (const float*)d_in[1];
    float* out = (float*)d_out;

    int Ntok  = in_sizes[0] / H;     // 16384
    int n_sel = Ntok * TOPK;         // 131072

    cudaFuncSetAttribute(gate_mma, cudaFuncAttributeMaxDynamicSharedMemorySize, SMEM_B);

    wsplit<<<64, 256>>>(W);
    gate_mma<<<Ntok / TILE_M, 256, SMEM_B>>>(x, out, Ntok);
    fixup_kernel<<<128, 256>>>(x, W, out, Ntok);
    loss_kernel<<<1, 64>>>(out + (size_t)2 * n_sel, Ntok);
}